// round 9
// baseline (speedup 1.0000x reference)
#include <cuda_runtime.h>
#include <cstdint>

#define NN 100000
#define EE 1600000
#define HF 128
#define GG 128
#define LL 4
#define EPS_BN 1e-5f
#define BM 128
#define BK 16
#define SCAN_B 512
#define NB ((NN + SCAN_B - 1) / SCAN_B)   // 196
#define NTILE ((NN + BM - 1) / BM)        // 782
#define ASTR 20                            // As row stride (16 + 4 pad)
#define BSTR 132                           // Bs row stride (128 + 4 pad)

// ---------------- scratch (static device globals; no allocs allowed) ----------
__device__ float g_h[(size_t)NN * HF];      // raw h (gather input)
__device__ float g_h_hi[(size_t)NN * HF];   // tf32 hi of h
__device__ float g_h_lo[(size_t)NN * HF];   // tf32 lo of h
__device__ float g_agg_hi[(size_t)NN * HF]; // tf32 hi of neighbor mean
__device__ float g_agg_lo[(size_t)NN * HF]; // tf32 lo of neighbor mean
__device__ float g_rst[(size_t)NN * HF];    // pre-BN layer output
__device__ float g_ws_hi[LL * HF * HF];
__device__ float g_ws_lo[LL * HF * HF];
__device__ float g_wn_hi[LL * HF * HF];
__device__ float g_wn_lo[LL * HF * HF];
__device__ float g_rdeg[NN];
__device__ float g_cnt[GG];
__device__ float g_stats[LL * 2 * HF];
__device__ float g_norm[LL * 2 * HF];
__device__ float g_pool[GG * LL * HF];
// CSR scratch
__device__ int g_cnt_i[NN];
__device__ int g_rowptr[NN];
__device__ int g_cur[NN];
__device__ int g_bsum[SCAN_B];
__device__ int g_eidx[EE];

__device__ __forceinline__ void red_add_v4(float* a, float4 v) {
    asm volatile("red.global.add.v4.f32 [%0], {%1,%2,%3,%4};"
                 :: "l"(a), "f"(v.x), "f"(v.y), "f"(v.z), "f"(v.w) : "memory");
}

__device__ __forceinline__ uint32_t f2tf32(float x) {
    uint32_t r;
    asm("cvt.rna.tf32.f32 %0, %1;" : "=r"(r) : "f"(x));
    return r;
}

__device__ __forceinline__ void tf32_split(float x, float& hi, float& lo) {
    uint32_t h = f2tf32(x);
    hi = __uint_as_float(h);
    lo = __uint_as_float(f2tf32(x - hi));
}

__device__ __forceinline__ void split4(float4 v, float4& hi, float4& lo) {
    tf32_split(v.x, hi.x, lo.x);
    tf32_split(v.y, hi.y, lo.y);
    tf32_split(v.z, hi.z, lo.z);
    tf32_split(v.w, hi.w, lo.w);
}

#define MMA_TF32(C, A0, A1, A2, A3, B0, B1)                              \
    asm volatile("mma.sync.aligned.m16n8k8.row.col.f32.tf32.tf32.f32 "   \
                 "{%0,%1,%2,%3}, {%4,%5,%6,%7}, {%8,%9}, {%0,%1,%2,%3};" \
                 : "+f"((C)[0]), "+f"((C)[1]), "+f"((C)[2]), "+f"((C)[3])\
                 : "r"(A0), "r"(A1), "r"(A2), "r"(A3), "r"(B0), "r"(B1))

// ---------------- init: h0 = emb[in_feat] (+ tf32 split) -----------------------
__global__ void k_init(const int* __restrict__ feat, const float* __restrict__ emb) {
    int idx = blockIdx.x * blockDim.x + threadIdx.x;
    if (idx >= NN * 32) return;
    int node = idx >> 5, q = idx & 31;
    int f = __ldg(&feat[node]);
    float4 v = __ldg((const float4*)(emb + (size_t)f * HF) + q);
    size_t off = (size_t)node * HF;
    *((float4*)(g_h + off) + q) = v;
    float4 hi, lo;
    split4(v, hi, lo);
    *((float4*)(g_h_hi + off) + q) = hi;
    *((float4*)(g_h_lo + off) + q) = lo;
}

// ---------------- one-shot weight split ----------------------------------------
__global__ void k_wsplit(const float* __restrict__ Ws, const float* __restrict__ Wn) {
    int i = blockIdx.x * blockDim.x + threadIdx.x;
    if (i >= LL * HF * HF) return;
    float hi, lo;
    tf32_split(__ldg(&Ws[i]), hi, lo);
    g_ws_hi[i] = hi; g_ws_lo[i] = lo;
    tf32_split(__ldg(&Wn[i]), hi, lo);
    g_wn_hi[i] = hi; g_wn_lo[i] = lo;
}

// ---------------- CSR build ----------------------------------------------------
__global__ void k_hist(const int* __restrict__ dst) {
    int e = blockIdx.x * blockDim.x + threadIdx.x;
    if (e < EE) atomicAdd(&g_cnt_i[__ldg(&dst[e])], 1);
}

__global__ void k_scan1() {
    __shared__ int sh[SCAN_B];
    int t = threadIdx.x;
    int i = blockIdx.x * SCAN_B + t;
    int v = (i < NN) ? g_cnt_i[i] : 0;
    sh[t] = v;
    __syncthreads();
    #pragma unroll
    for (int off = 1; off < SCAN_B; off <<= 1) {
        int x = (t >= off) ? sh[t - off] : 0;
        __syncthreads();
        sh[t] += x;
        __syncthreads();
    }
    if (i < NN) g_rowptr[i] = sh[t] - v;
    if (t == SCAN_B - 1) g_bsum[blockIdx.x] = sh[t];
}

__global__ void k_scan2() {
    __shared__ int sh[256];
    int t = threadIdx.x;
    int v = (t < NB) ? g_bsum[t] : 0;
    sh[t] = v;
    __syncthreads();
    #pragma unroll
    for (int off = 1; off < 256; off <<= 1) {
        int x = (t >= off) ? sh[t - off] : 0;
        __syncthreads();
        sh[t] += x;
        __syncthreads();
    }
    if (t < NB) g_bsum[t] = sh[t] - v;
}

__global__ void k_scan3() {
    int i = blockIdx.x * blockDim.x + threadIdx.x;
    if (i >= NN) return;
    int base = g_rowptr[i] + g_bsum[i / SCAN_B];
    g_rowptr[i] = base;
    g_cur[i] = base;
    g_rdeg[i] = 1.0f / fmaxf((float)g_cnt_i[i], 1.0f);
}

__global__ void k_scatter(const int* __restrict__ src, const int* __restrict__ dst) {
    int e = blockIdx.x * blockDim.x + threadIdx.x;
    if (e >= EE) return;
    int d = __ldg(&dst[e]);
    int pos = atomicAdd(&g_cur[d], 1);
    g_eidx[pos] = __ldg(&src[e]);
}

// ---------------- graph node counts --------------------------------------------
__global__ void k_cnt(const int* __restrict__ gid) {
    __shared__ float sh[GG];
    int t = threadIdx.x;
    if (t < GG) sh[t] = 0.f;
    __syncthreads();
    int i = blockIdx.x * blockDim.x + t;
    if (i < NN) atomicAdd(&sh[__ldg(&gid[i])], 1.0f);
    __syncthreads();
    if (t < GG && sh[t] != 0.f) atomicAdd(&g_cnt[t], sh[t]);
}

// ---------------- aggregation: CSR gather, warp per node, split output ---------
__global__ __launch_bounds__(256) void k_gather() {
    int w = (blockIdx.x * blockDim.x + threadIdx.x) >> 5;
    if (w >= NN) return;
    int lane = threadIdx.x & 31;
    int beg = __ldg(&g_rowptr[w]);
    int cnt = __ldg(&g_cnt_i[w]);
    float4 a0 = make_float4(0.f, 0.f, 0.f, 0.f);
    float4 a1 = make_float4(0.f, 0.f, 0.f, 0.f);
    for (int base = 0; base < cnt; base += 32) {
        int idx = (base + lane < cnt) ? __ldg(&g_eidx[beg + base + lane]) : 0;
        int m = min(32, cnt - base);
        int j = 0;
        for (; j + 1 < m; j += 2) {
            int s0 = __shfl_sync(0xffffffffu, idx, j);
            int s1 = __shfl_sync(0xffffffffu, idx, j + 1);
            float4 v0 = __ldg((const float4*)(g_h + (size_t)s0 * HF) + lane);
            float4 v1 = __ldg((const float4*)(g_h + (size_t)s1 * HF) + lane);
            a0.x += v0.x; a0.y += v0.y; a0.z += v0.z; a0.w += v0.w;
            a1.x += v1.x; a1.y += v1.y; a1.z += v1.z; a1.w += v1.w;
        }
        if (j < m) {
            int s0 = __shfl_sync(0xffffffffu, idx, j);
            float4 v0 = __ldg((const float4*)(g_h + (size_t)s0 * HF) + lane);
            a0.x += v0.x; a0.y += v0.y; a0.z += v0.z; a0.w += v0.w;
        }
    }
    float r = __ldg(&g_rdeg[w]);
    float4 o;
    o.x = (a0.x + a1.x) * r;
    o.y = (a0.y + a1.y) * r;
    o.z = (a0.z + a1.z) * r;
    o.w = (a0.w + a1.w) * r;
    float4 hi, lo;
    split4(o, hi, lo);
    *((float4*)(g_agg_hi + (size_t)w * HF) + lane) = hi;
    *((float4*)(g_agg_lo + (size_t)w * HF) + lane) = lo;
}

// ---------------- tensor-core GEMM (3xTF32, preconverted operands) -------------
// 256 thr = 8 warps (2 m x 4 n); warp tile 64x32 via m16n8k8 atoms.
__global__ __launch_bounds__(256) void k_gemm(
    const float* __restrict__ Wh0, const float* __restrict__ Wl0,
    const float* __restrict__ Wh1, const float* __restrict__ Wl1,
    const float* __restrict__ bias, const float* __restrict__ pw, int l)
{
    __shared__ float As_hi[BM * ASTR];
    __shared__ float As_lo[BM * ASTR];
    __shared__ float Bs_hi[BK * BSTR];
    __shared__ float Bs_lo[BK * BSTR];
    __shared__ float s_sum[HF];
    __shared__ float s_sq[HF];

    int t = threadIdx.x;
    int lane = t & 31, wid = t >> 5;
    int wm = wid >> 2;
    int wn = wid & 3;
    int g = lane >> 2, tg = lane & 3;
    int row0 = blockIdx.x * BM;

    if (t < HF) { s_sum[t] = 0.f; s_sq[t] = 0.f; }

    float c[4][4][4];
    #pragma unroll
    for (int ma = 0; ma < 4; ma++)
        #pragma unroll
        for (int na = 0; na < 4; na++)
            #pragma unroll
            for (int q = 0; q < 4; q++) c[ma][na][q] = 0.f;

    #pragma unroll
    for (int phase = 0; phase < 2; phase++) {
        const float* Ah = phase ? g_agg_hi : g_h_hi;
        const float* Al = phase ? g_agg_lo : g_h_lo;
        const float* Wh = phase ? Wh1 : Wh0;
        const float* Wl = phase ? Wl1 : Wl0;
        for (int k0 = 0; k0 < HF; k0 += BK) {
            __syncthreads();
            // --- A tile: 128 rows x 16 k, hi/lo vector copies ---
            #pragma unroll
            for (int i = 0; i < 2; i++) {
                int j = i * 256 + t;          // 0..511 float4-granules
                int m = j >> 2;
                int c4 = j & 3;
                int row = row0 + m;
                float4 hi = make_float4(0.f, 0.f, 0.f, 0.f);
                float4 lo = make_float4(0.f, 0.f, 0.f, 0.f);
                if (row < NN) {
                    hi = __ldg((const float4*)(Ah + (size_t)row * HF + k0) + c4);
                    lo = __ldg((const float4*)(Al + (size_t)row * HF + k0) + c4);
                }
                *(float4*)&As_hi[m * ASTR + c4 * 4] = hi;
                *(float4*)&As_lo[m * ASTR + c4 * 4] = lo;
            }
            // --- B tile: 16 k x 128 n, hi/lo vector copies ---
            #pragma unroll
            for (int i = 0; i < 2; i++) {
                int j = i * 256 + t;
                int kk = j >> 5;
                int c4 = j & 31;
                float4 hi = __ldg((const float4*)(Wh + (size_t)(k0 + kk) * HF) + c4);
                float4 lo = __ldg((const float4*)(Wl + (size_t)(k0 + kk) * HF) + c4);
                *(float4*)&Bs_hi[kk * BSTR + c4 * 4] = hi;
                *(float4*)&Bs_lo[kk * BSTR + c4 * 4] = lo;
            }
            __syncthreads();
            #pragma unroll
            for (int ks = 0; ks < 2; ks++) {
                int kc = ks * 8 + tg;
                uint32_t ah[4][4], al[4][4];
                #pragma unroll
                for (int ma = 0; ma < 4; ma++) {
                    int r = wm * 64 + ma * 16 + g;
                    ah[ma][0] = __float_as_uint(As_hi[r * ASTR + kc]);
                    ah[ma][1] = __float_as_uint(As_hi[(r + 8) * ASTR + kc]);
                    ah[ma][2] = __float_as_uint(As_hi[r * ASTR + kc + 4]);
                    ah[ma][3] = __float_as_uint(As_hi[(r + 8) * ASTR + kc + 4]);
                    al[ma][0] = __float_as_uint(As_lo[r * ASTR + kc]);
                    al[ma][1] = __float_as_uint(As_lo[(r + 8) * ASTR + kc]);
                    al[ma][2] = __float_as_uint(As_lo[r * ASTR + kc + 4]);
                    al[ma][3] = __float_as_uint(As_lo[(r + 8) * ASTR + kc + 4]);
                }
                #pragma unroll
                for (int na = 0; na < 4; na++) {
                    int nc = wn * 32 + na * 8 + g;
                    uint32_t bh0 = __float_as_uint(Bs_hi[(ks * 8 + tg) * BSTR + nc]);
                    uint32_t bh1 = __float_as_uint(Bs_hi[(ks * 8 + tg + 4) * BSTR + nc]);
                    uint32_t bl0 = __float_as_uint(Bs_lo[(ks * 8 + tg) * BSTR + nc]);
                    uint32_t bl1 = __float_as_uint(Bs_lo[(ks * 8 + tg + 4) * BSTR + nc]);
                    #pragma unroll
                    for (int ma = 0; ma < 4; ma++) {
                        MMA_TF32(c[ma][na], ah[ma][0], ah[ma][1], ah[ma][2], ah[ma][3], bh0, bh1);
                        MMA_TF32(c[ma][na], ah[ma][0], ah[ma][1], ah[ma][2], ah[ma][3], bl0, bl1);
                        MMA_TF32(c[ma][na], al[ma][0], al[ma][1], al[ma][2], al[ma][3], bh0, bh1);
                    }
                }
            }
        }
    }
    __syncthreads();

    // --- epilogue: bias, PReLU, store rst, per-channel stats ---
    float ps[8] = {0}, pq[8] = {0};
    float bc[8], pc[8];
    #pragma unroll
    for (int na = 0; na < 4; na++) {
        int col = wn * 32 + na * 8 + 2 * tg;
        float2 b2 = __ldg((const float2*)(bias + col));
        float2 p2 = __ldg((const float2*)(pw + col));
        bc[na * 2] = b2.x; bc[na * 2 + 1] = b2.y;
        pc[na * 2] = p2.x; pc[na * 2 + 1] = p2.y;
    }
    #pragma unroll
    for (int ma = 0; ma < 4; ma++) {
        int ra = row0 + wm * 64 + ma * 16 + g;
        int rb = ra + 8;
        #pragma unroll
        for (int half = 0; half < 2; half++) {
            int row = half ? rb : ra;
            if (row < NN) {
                #pragma unroll
                for (int na = 0; na < 4; na++) {
                    int col = wn * 32 + na * 8 + 2 * tg;
                    float x0 = c[ma][na][half * 2 + 0] + bc[na * 2];
                    float x1 = c[ma][na][half * 2 + 1] + bc[na * 2 + 1];
                    x0 = x0 > 0.f ? x0 : pc[na * 2] * x0;
                    x1 = x1 > 0.f ? x1 : pc[na * 2 + 1] * x1;
                    *((float2*)(g_rst + (size_t)row * HF + col)) = make_float2(x0, x1);
                    ps[na * 2] += x0;     pq[na * 2] += x0 * x0;
                    ps[na * 2 + 1] += x1; pq[na * 2 + 1] += x1 * x1;
                }
            }
        }
    }
    #pragma unroll
    for (int na = 0; na < 4; na++) {
        int col = wn * 32 + na * 8 + 2 * tg;
        atomicAdd(&s_sum[col], ps[na * 2]);
        atomicAdd(&s_sum[col + 1], ps[na * 2 + 1]);
        atomicAdd(&s_sq[col], pq[na * 2]);
        atomicAdd(&s_sq[col + 1], pq[na * 2 + 1]);
    }
    __syncthreads();
    if (t < HF) {
        atomicAdd(&g_stats[l * 2 * HF + t], s_sum[t]);
        atomicAdd(&g_stats[l * 2 * HF + HF + t], s_sq[t]);
    }
}

// ---------------- BN stats finalize --------------------------------------------
__global__ void k_finalize(const float* __restrict__ gamma,
                           const float* __restrict__ beta, int l) {
    int c = threadIdx.x;
    float s = g_stats[l * 2 * HF + c];
    float q = g_stats[l * 2 * HF + HF + c];
    const float inv_n = 1.0f / (float)NN;
    float mu = s * inv_n;
    float var = fmaf(-mu, mu, q * inv_n);
    float rs = rsqrtf(var + EPS_BN);
    float sc = __ldg(&gamma[c]) * rs;
    float sh = fmaf(-mu, sc, __ldg(&beta[c]));
    g_norm[l * 2 * HF + c] = sc;
    g_norm[l * 2 * HF + HF + c] = sh;
}

// ---------------- apply BN, write h_next (+split), pooled red with run-fusion --
__global__ void k_apply(const int* __restrict__ gid, int l) {
    int w = (blockIdx.x * blockDim.x + threadIdx.x) >> 5;
    int n0 = w * 8;
    if (n0 >= NN) return;
    int lane = threadIdx.x & 31;
    float4 sc = *((const float4*)(g_norm + l * 2 * HF) + lane);
    float4 sh = *((const float4*)(g_norm + l * 2 * HF + HF) + lane);
    float4 acc = make_float4(0.f, 0.f, 0.f, 0.f);
    int cur = __ldg(&gid[n0]);
    int nend = min(n0 + 8, NN);
    bool last = (l == LL - 1);
    for (int n = n0; n < nend; n++) {
        float4 v = *((const float4*)(g_rst + (size_t)n * HF) + lane);
        v.x = fmaf(v.x, sc.x, sh.x);
        v.y = fmaf(v.y, sc.y, sh.y);
        v.z = fmaf(v.z, sc.z, sh.z);
        v.w = fmaf(v.w, sc.w, sh.w);
        if (!last) {
            size_t off = (size_t)n * HF;
            *((float4*)(g_h + off) + lane) = v;
            float4 hi, lo;
            split4(v, hi, lo);
            *((float4*)(g_h_hi + off) + lane) = hi;
            *((float4*)(g_h_lo + off) + lane) = lo;
        }
        int gg = __ldg(&gid[n]);
        if (gg != cur) {
            red_add_v4((float*)((float4*)(g_pool + (size_t)cur * (LL * HF) + l * HF) + lane), acc);
            acc = make_float4(0.f, 0.f, 0.f, 0.f);
            cur = gg;
        }
        acc.x += v.x; acc.y += v.y; acc.z += v.z; acc.w += v.w;
    }
    red_add_v4((float*)((float4*)(g_pool + (size_t)cur * (LL * HF) + l * HF) + lane), acc);
}

// ---------------- final: divide pool by graph counts ---------------------------
__global__ void k_out(float* __restrict__ out) {
    int i = blockIdx.x * blockDim.x + threadIdx.x;
    if (i < GG * LL * HF) {
        int g = i >> 9;
        out[i] = g_pool[i] / fmaxf(g_cnt[g], 1.0f);
    }
}

// ---------------- launch --------------------------------------------------------
extern "C" void kernel_launch(void* const* d_in, const int* in_sizes, int n_in,
                              void* d_out, int out_size) {
    const int*   in_feat = (const int*)d_in[0];
    const int*   src     = (const int*)d_in[1];
    const int*   dst     = (const int*)d_in[2];
    const int*   gid     = (const int*)d_in[3];
    const float* emb     = (const float*)d_in[4];
    const float* W_self  = (const float*)d_in[5];
    const float* W_neigh = (const float*)d_in[6];
    const float* bias    = (const float*)d_in[7];
    const float* gamma   = (const float*)d_in[8];
    const float* beta    = (const float*)d_in[9];
    const float* prelu   = (const float*)d_in[10];

    void *p_cnti, *p_cnt, *p_pool, *p_stats;
    void *p_wsh, *p_wsl, *p_wnh, *p_wnl;
    cudaGetSymbolAddress(&p_cnti, g_cnt_i);
    cudaGetSymbolAddress(&p_cnt, g_cnt);
    cudaGetSymbolAddress(&p_pool, g_pool);
    cudaGetSymbolAddress(&p_stats, g_stats);
    cudaGetSymbolAddress(&p_wsh, g_ws_hi);
    cudaGetSymbolAddress(&p_wsl, g_ws_lo);
    cudaGetSymbolAddress(&p_wnh, g_wn_hi);
    cudaGetSymbolAddress(&p_wnl, g_wn_lo);

    cudaMemsetAsync(p_cnti, 0, NN * sizeof(int));
    cudaMemsetAsync(p_cnt, 0, GG * sizeof(float));
    cudaMemsetAsync(p_pool, 0, (size_t)GG * LL * HF * sizeof(float));
    cudaMemsetAsync(p_stats, 0, (size_t)LL * 2 * HF * sizeof(float));

    k_init<<<(NN * 32 + 255) / 256, 256>>>(in_feat, emb);
    k_wsplit<<<(LL * HF * HF + 255) / 256, 256>>>(W_self, W_neigh);
    k_hist<<<(EE + 255) / 256, 256>>>(dst);
    k_scan1<<<NB, SCAN_B>>>();
    k_scan2<<<1, 256>>>();
    k_scan3<<<(NN + 255) / 256, 256>>>();
    k_scatter<<<(EE + 255) / 256, 256>>>(src, dst);
    k_cnt<<<(NN + 255) / 256, 256>>>(gid);

    for (int l = 0; l < LL; l++) {
        size_t wo = (size_t)l * HF * HF;
        k_gather<<<(NN * 32 + 255) / 256, 256>>>();
        k_gemm<<<NTILE, 256>>>((const float*)p_wsh + wo, (const float*)p_wsl + wo,
                               (const float*)p_wnh + wo, (const float*)p_wnl + wo,
                               bias + l * HF, prelu + l * HF, l);
        k_finalize<<<1, HF>>>(gamma + l * HF, beta + l * HF, l);
        k_apply<<<(((NN + 7) / 8) * 32 + 255) / 256, 256>>>(gid, l);
    }
    k_out<<<(GG * LL * HF + 255) / 256, 256>>>((float*)d_out);
}

// round 10
// speedup vs baseline: 1.2447x; 1.2447x over previous
#include <cuda_runtime.h>

#define NN 100000
#define EE 1600000
#define HF 128
#define GG 128
#define LL 4
#define EPS_BN 1e-5f
#define BM 128
#define BK 32
#define ASTRIDE 132
#define SCAN_B 512
#define NB ((NN + SCAN_B - 1) / SCAN_B)   // 196
#define NTILE ((NN + BM - 1) / BM)        // 782

// ---------------- scratch (static device globals; no allocs allowed) ----------
__device__ float g_h[(size_t)NN * HF];       // buffer A (emb / raw rst ping-pong)
__device__ float g_rst[(size_t)NN * HF];     // buffer B
__device__ float g_agg[(size_t)NN * HF];     // BN-folded neighbor means
__device__ float g_rdeg[NN];
__device__ float g_cnt[GG];
__device__ float g_stats[LL * 2 * HF];       // per-layer [sum | sumsq] of raw rst
__device__ float g_norm2[(LL + 1) * 2 * HF]; // slot 0 = identity; slot l+1 = BN(l)
__device__ float g_pool[GG * LL * HF];       // RAW rst pooling accumulator
// CSR scratch
__device__ int g_cnt_i[NN];
__device__ int g_rowptr[NN];
__device__ int g_cur[NN];
__device__ int g_bsum[SCAN_B];
__device__ int g_eidx[EE];

__device__ __forceinline__ void red_add_v4(float* a, float x, float y, float z, float w) {
    asm volatile("red.global.add.v4.f32 [%0], {%1,%2,%3,%4};"
                 :: "l"(a), "f"(x), "f"(y), "f"(z), "f"(w) : "memory");
}

// ---------------- init: h0 = emb[in_feat] -------------------------------------
__global__ void k_init(const int* __restrict__ feat, const float* __restrict__ emb) {
    int idx = blockIdx.x * blockDim.x + threadIdx.x;
    if (idx >= NN * 32) return;
    int node = idx >> 5, q = idx & 31;
    int f = __ldg(&feat[node]);
    float4 v = __ldg((const float4*)(emb + (size_t)f * HF) + q);
    *((float4*)(g_h + (size_t)node * HF) + q) = v;
}

// ---------------- CSR build ----------------------------------------------------
__global__ void k_hist(const int* __restrict__ dst) {
    int e = blockIdx.x * blockDim.x + threadIdx.x;
    if (e < EE) atomicAdd(&g_cnt_i[__ldg(&dst[e])], 1);
}

__global__ void k_scan1() {
    __shared__ int sh[SCAN_B];
    int t = threadIdx.x;
    int i = blockIdx.x * SCAN_B + t;
    int v = (i < NN) ? g_cnt_i[i] : 0;
    sh[t] = v;
    __syncthreads();
    #pragma unroll
    for (int off = 1; off < SCAN_B; off <<= 1) {
        int x = (t >= off) ? sh[t - off] : 0;
        __syncthreads();
        sh[t] += x;
        __syncthreads();
    }
    if (i < NN) g_rowptr[i] = sh[t] - v;
    if (t == SCAN_B - 1) g_bsum[blockIdx.x] = sh[t];
}

__global__ void k_scan2() {
    __shared__ int sh[256];
    int t = threadIdx.x;
    int v = (t < NB) ? g_bsum[t] : 0;
    sh[t] = v;
    __syncthreads();
    #pragma unroll
    for (int off = 1; off < 256; off <<= 1) {
        int x = (t >= off) ? sh[t - off] : 0;
        __syncthreads();
        sh[t] += x;
        __syncthreads();
    }
    if (t < NB) g_bsum[t] = sh[t] - v;
}

__global__ void k_scan3() {
    int i = blockIdx.x * blockDim.x + threadIdx.x;
    if (i >= NN) return;
    int base = g_rowptr[i] + g_bsum[i / SCAN_B];
    g_rowptr[i] = base;
    g_cur[i] = base;
    g_rdeg[i] = 1.0f / fmaxf((float)g_cnt_i[i], 1.0f);
}

__global__ void k_scatter(const int* __restrict__ src, const int* __restrict__ dst) {
    int e = blockIdx.x * blockDim.x + threadIdx.x;
    if (e >= EE) return;
    int d = __ldg(&dst[e]);
    int pos = atomicAdd(&g_cur[d], 1);
    g_eidx[pos] = __ldg(&src[e]);
}

// ---------------- graph node counts + identity norm slot -----------------------
__global__ void k_cnt(const int* __restrict__ gid) {
    __shared__ float sh[GG];
    int t = threadIdx.x;
    if (t < GG) sh[t] = 0.f;
    __syncthreads();
    int i = blockIdx.x * blockDim.x + t;
    if (i < NN) atomicAdd(&sh[__ldg(&gid[i])], 1.0f);
    __syncthreads();
    if (t < GG && sh[t] != 0.f) atomicAdd(&g_cnt[t], sh[t]);
}

__global__ void k_norm0() {
    int c = threadIdx.x;
    g_norm2[c] = 1.0f;
    g_norm2[HF + c] = 0.0f;
}

// ---------------- aggregation: CSR gather of RAW X, BN fold applied post-mean --
__global__ __launch_bounds__(256) void k_gather(const float* __restrict__ X, int slot) {
    int w = (blockIdx.x * blockDim.x + threadIdx.x) >> 5;
    if (w >= NN) return;
    int lane = threadIdx.x & 31;
    int beg = __ldg(&g_rowptr[w]);
    int cnt = __ldg(&g_cnt_i[w]);
    float4 a0 = make_float4(0.f, 0.f, 0.f, 0.f);
    float4 a1 = make_float4(0.f, 0.f, 0.f, 0.f);
    for (int base = 0; base < cnt; base += 32) {
        int idx = (base + lane < cnt) ? __ldg(&g_eidx[beg + base + lane]) : 0;
        int m = min(32, cnt - base);
        int j = 0;
        for (; j + 1 < m; j += 2) {
            int s0 = __shfl_sync(0xffffffffu, idx, j);
            int s1 = __shfl_sync(0xffffffffu, idx, j + 1);
            float4 v0 = __ldg((const float4*)(X + (size_t)s0 * HF) + lane);
            float4 v1 = __ldg((const float4*)(X + (size_t)s1 * HF) + lane);
            a0.x += v0.x; a0.y += v0.y; a0.z += v0.z; a0.w += v0.w;
            a1.x += v1.x; a1.y += v1.y; a1.z += v1.z; a1.w += v1.w;
        }
        if (j < m) {
            int s0 = __shfl_sync(0xffffffffu, idx, j);
            float4 v0 = __ldg((const float4*)(X + (size_t)s0 * HF) + lane);
            a0.x += v0.x; a0.y += v0.y; a0.z += v0.z; a0.w += v0.w;
        }
    }
    float r = __ldg(&g_rdeg[w]);
    float dz = (cnt > 0) ? 1.0f : 0.0f;   // zero-degree: mean is exactly 0 in h-space
    const float* nsc = g_norm2 + slot * 2 * HF;
    float4 sc = *((const float4*)nsc + lane);
    float4 sh = *((const float4*)(nsc + HF) + lane);
    float4 o;
    o.x = fmaf((a0.x + a1.x) * r, sc.x, sh.x * dz);
    o.y = fmaf((a0.y + a1.y) * r, sc.y, sh.y * dz);
    o.z = fmaf((a0.z + a1.z) * r, sc.z, sh.z * dz);
    o.w = fmaf((a0.w + a1.w) * r, sc.w, sh.w * dz);
    *((float4*)(g_agg + (size_t)w * HF) + lane) = o;
}

// ---------------- fused GEMM: rst = BN(X)@Ws + agg@Wn + b, PReLU, stats, pool --
__global__ __launch_bounds__(256) void k_gemm(
    const float* __restrict__ X, float* __restrict__ R,
    const float* __restrict__ Ws, const float* __restrict__ Wn,
    const float* __restrict__ bias, const float* __restrict__ pw,
    const int* __restrict__ gid, int l)
{
    __shared__ float As[BK * ASTRIDE];
    __shared__ float Bs[BK * HF];

    int t = threadIdx.x;
    int tx = t & 15, ty = t >> 4;
    int row0 = blockIdx.x * BM;
    const float* nsc = g_norm2 + l * 2 * HF;
    const float* nsh = nsc + HF;

    float acc[8][8];
    #pragma unroll
    for (int r = 0; r < 8; r++)
        #pragma unroll
        for (int c = 0; c < 8; c++) acc[r][c] = 0.f;

    #pragma unroll
    for (int phase = 0; phase < 2; phase++) {
        const float* A = phase ? g_agg : X;
        const float* W = phase ? Wn : Ws;
        for (int k0 = 0; k0 < HF; k0 += BK) {
            #pragma unroll
            for (int i = 0; i < 4; i++) {
                int j = i * 256 + t;
                int m = j >> 3;
                int kk = (j & 7) << 2;
                int row = row0 + m;
                float4 a = make_float4(0.f, 0.f, 0.f, 0.f);
                if (row < NN) {
                    a = __ldg((const float4*)(A + (size_t)row * HF + k0) + (j & 7));
                    if (phase == 0) {   // fold BN of previous layer into self path
                        float4 sc = __ldg((const float4*)nsc + (k0 >> 2) + (j & 7));
                        float4 sh = __ldg((const float4*)nsh + (k0 >> 2) + (j & 7));
                        a.x = fmaf(a.x, sc.x, sh.x);
                        a.y = fmaf(a.y, sc.y, sh.y);
                        a.z = fmaf(a.z, sc.z, sh.z);
                        a.w = fmaf(a.w, sc.w, sh.w);
                    }
                }
                As[(kk + 0) * ASTRIDE + m] = a.x;
                As[(kk + 1) * ASTRIDE + m] = a.y;
                As[(kk + 2) * ASTRIDE + m] = a.z;
                As[(kk + 3) * ASTRIDE + m] = a.w;
            }
            #pragma unroll
            for (int i = 0; i < 4; i++) {
                int j = i * 256 + t;
                int kk = j >> 5;
                int c4 = j & 31;
                float4 b4 = __ldg((const float4*)(W + (size_t)(k0 + kk) * HF) + c4);
                *((float4*)(Bs + kk * HF) + c4) = b4;
            }
            __syncthreads();
            #pragma unroll
            for (int kk = 0; kk < BK; kk++) {
                float4 a0 = *(const float4*)&As[kk * ASTRIDE + ty * 8];
                float4 a1 = *(const float4*)&As[kk * ASTRIDE + ty * 8 + 4];
                float4 b0 = *(const float4*)&Bs[kk * HF + tx * 8];
                float4 b1 = *(const float4*)&Bs[kk * HF + tx * 8 + 4];
                float ar[8] = {a0.x, a0.y, a0.z, a0.w, a1.x, a1.y, a1.z, a1.w};
                float br[8] = {b0.x, b0.y, b0.z, b0.w, b1.x, b1.y, b1.z, b1.w};
                #pragma unroll
                for (int r = 0; r < 8; r++)
                    #pragma unroll
                    for (int c = 0; c < 8; c++)
                        acc[r][c] = fmaf(ar[r], br[c], acc[r][c]);
            }
            __syncthreads();
        }
    }

    // --- epilogue: bias, PReLU, store raw rst, stats, run-fused raw pooling ----
    float bc[8], pc[8];
    #pragma unroll
    for (int c = 0; c < 8; c++) {
        bc[c] = __ldg(&bias[tx * 8 + c]);
        pc[c] = __ldg(&pw[tx * 8 + c]);
    }
    float ps[8] = {0}, pq[8] = {0};
    float pa[8] = {0};
    int curg = -1;
    #pragma unroll
    for (int r = 0; r < 8; r++) {
        int row = row0 + ty * 8 + r;
        if (row < NN) {
            float v[8];
            #pragma unroll
            for (int c = 0; c < 8; c++) {
                float x = acc[r][c] + bc[c];
                x = x > 0.f ? x : pc[c] * x;
                v[c] = x;
                ps[c] += x;
                pq[c] += x * x;
            }
            float4* o = (float4*)(R + (size_t)row * HF + tx * 8);
            o[0] = make_float4(v[0], v[1], v[2], v[3]);
            o[1] = make_float4(v[4], v[5], v[6], v[7]);
            int g = __ldg(&gid[row]);
            if (g != curg) {
                if (curg >= 0) {
                    float* pp = g_pool + (size_t)curg * (LL * HF) + l * HF + tx * 8;
                    red_add_v4(pp, pa[0], pa[1], pa[2], pa[3]);
                    red_add_v4(pp + 4, pa[4], pa[5], pa[6], pa[7]);
                }
                curg = g;
                #pragma unroll
                for (int c = 0; c < 8; c++) pa[c] = v[c];
            } else {
                #pragma unroll
                for (int c = 0; c < 8; c++) pa[c] += v[c];
            }
        }
    }
    if (curg >= 0) {
        float* pp = g_pool + (size_t)curg * (LL * HF) + l * HF + tx * 8;
        red_add_v4(pp, pa[0], pa[1], pa[2], pa[3]);
        red_add_v4(pp + 4, pa[4], pa[5], pa[6], pa[7]);
    }

    __syncthreads();   // done with Bs as W tile; reuse for stat reduction
    #pragma unroll
    for (int c = 0; c < 8; c++) {
        Bs[ty * HF + tx * 8 + c] = ps[c];
        Bs[2048 + ty * HF + tx * 8 + c] = pq[c];
    }
    __syncthreads();
    if (t < HF) {
        float s = 0.f, q = 0.f;
        #pragma unroll
        for (int r = 0; r < 16; r++) {
            s += Bs[r * HF + t];
            q += Bs[2048 + r * HF + t];
        }
        atomicAdd(&g_stats[l * 2 * HF + t], s);
        atomicAdd(&g_stats[l * 2 * HF + HF + t], q);
    }
}

// ---------------- BN stats finalize -> norm slot l+1 ---------------------------
__global__ void k_finalize(const float* __restrict__ gamma,
                           const float* __restrict__ beta, int l) {
    int c = threadIdx.x;
    float s = g_stats[l * 2 * HF + c];
    float q = g_stats[l * 2 * HF + HF + c];
    const float inv_n = 1.0f / (float)NN;
    float mu = s * inv_n;
    float var = fmaf(-mu, mu, q * inv_n);
    float rs = rsqrtf(var + EPS_BN);
    float sc = __ldg(&gamma[c]) * rs;
    float sh = fmaf(-mu, sc, __ldg(&beta[c]));
    g_norm2[(l + 1) * 2 * HF + c] = sc;
    g_norm2[(l + 1) * 2 * HF + HF + c] = sh;
}

// ---------------- final: mean over graph + deferred BN affine ------------------
__global__ void k_out(float* __restrict__ out) {
    int i = blockIdx.x * blockDim.x + threadIdx.x;
    if (i >= GG * LL * HF) return;
    int g = i >> 9;
    int l = (i >> 7) & 3;
    int c = i & 127;
    float cnt = g_cnt[g];
    float cz = (cnt > 0.f) ? 1.0f : 0.0f;
    float sc = g_norm2[(l + 1) * 2 * HF + c];
    float sh = g_norm2[(l + 1) * 2 * HF + HF + c];
    out[i] = fmaf(g_pool[i] / fmaxf(cnt, 1.0f), sc, sh * cz);
}

// ---------------- launch --------------------------------------------------------
extern "C" void kernel_launch(void* const* d_in, const int* in_sizes, int n_in,
                              void* d_out, int out_size) {
    const int*   in_feat = (const int*)d_in[0];
    const int*   src     = (const int*)d_in[1];
    const int*   dst     = (const int*)d_in[2];
    const int*   gid     = (const int*)d_in[3];
    const float* emb     = (const float*)d_in[4];
    const float* W_self  = (const float*)d_in[5];
    const float* W_neigh = (const float*)d_in[6];
    const float* bias    = (const float*)d_in[7];
    const float* gamma   = (const float*)d_in[8];
    const float* beta    = (const float*)d_in[9];
    const float* prelu   = (const float*)d_in[10];

    void *p_cnti, *p_cnt, *p_pool, *p_stats, *p_h, *p_rst;
    cudaGetSymbolAddress(&p_cnti, g_cnt_i);
    cudaGetSymbolAddress(&p_cnt, g_cnt);
    cudaGetSymbolAddress(&p_pool, g_pool);
    cudaGetSymbolAddress(&p_stats, g_stats);
    cudaGetSymbolAddress(&p_h, g_h);
    cudaGetSymbolAddress(&p_rst, g_rst);

    cudaMemsetAsync(p_cnti, 0, NN * sizeof(int));
    cudaMemsetAsync(p_cnt, 0, GG * sizeof(float));
    cudaMemsetAsync(p_pool, 0, (size_t)GG * LL * HF * sizeof(float));
    cudaMemsetAsync(p_stats, 0, (size_t)LL * 2 * HF * sizeof(float));

    k_init<<<(NN * 32 + 255) / 256, 256>>>(in_feat, emb);
    k_hist<<<(EE + 255) / 256, 256>>>(dst);
    k_scan1<<<NB, SCAN_B>>>();
    k_scan2<<<1, 256>>>();
    k_scan3<<<(NN + 255) / 256, 256>>>();
    k_scatter<<<(EE + 255) / 256, 256>>>(src, dst);
    k_cnt<<<(NN + 255) / 256, 256>>>(gid);
    k_norm0<<<1, HF>>>();

    for (int l = 0; l < LL; l++) {
        const float* Xin = (l & 1) ? (const float*)p_rst : (const float*)p_h;
        float*       Xout = (l & 1) ? (float*)p_h : (float*)p_rst;
        k_gather<<<(NN * 32 + 255) / 256, 256>>>(Xin, l);
        k_gemm<<<NTILE, 256>>>(Xin, Xout,
                               W_self + (size_t)l * HF * HF,
                               W_neigh + (size_t)l * HF * HF,
                               bias + l * HF, prelu + l * HF, gid, l);
        k_finalize<<<1, HF>>>(gamma + l * HF, beta + l * HF, l);
    }
    k_out<<<(GG * LL * HF + 255) / 256, 256>>>((float*)d_out);
}